// round 15
// baseline (speedup 1.0000x reference)
#include <cuda_runtime.h>
#include <cuda_fp16.h>
#include <cstdint>

#define NN_MAX   100000
#define F        128

// Scratch (fp16): A[n][j] = W1[:,:128]@h[n] + b1 ; B[n][j] = W1[:,128:]@h[n]
__device__ __half g_Ah[NN_MAX * F];
__device__ __half g_Bh[NN_MAX * F];

// fp16 b-fragments for m16n8k16 (row.col), uint2 per k-step:
//   b0 = {W[n][kc+2t], W[n][kc+2t+1]}, b1 = {W[n][kc+2t+8], W[n][kc+2t+9]},
//   n = ni*8 + (lane>>2), kc = ki*16
__device__ uint2 g_W2f[16 * 8 * 32];
__device__ uint2 g_W1f[32 * 8 * 32];

// ---------------------------------------------------------------------------
__device__ __forceinline__ uint32_t h2pack(float lo, float hi) {
    __half2 h = __floats2half2_rn(lo, hi);
    return *reinterpret_cast<uint32_t*>(&h);
}
__device__ __forceinline__ uint32_t h2u(__half2 h) {
    return *reinterpret_cast<uint32_t*>(&h);
}
__device__ __forceinline__ __half2 combh2(uint32_t a, uint32_t b, __half2 m) {
    __half2 ha = *reinterpret_cast<__half2*>(&a);
    __half2 hb = *reinterpret_cast<__half2*>(&b);
    const __half2 z = __float2half2_rn(0.0f);
    return __hmul2(__hmax2(__hadd2(ha, hb), z), m);
}

__device__ __forceinline__ void mma_f16(float& c0, float& c1, float& c2, float& c3,
                                        uint32_t a0, uint32_t a1, uint32_t a2, uint32_t a3,
                                        uint32_t b0, uint32_t b1)
{
    asm volatile(
        "mma.sync.aligned.m16n8k16.row.col.f32.f16.f16.f32 "
        "{%0,%1,%2,%3}, {%4,%5,%6,%7}, {%8,%9}, {%0,%1,%2,%3};\n"
        : "+f"(c0), "+f"(c1), "+f"(c2), "+f"(c3)
        : "r"(a0), "r"(a1), "r"(a2), "r"(a3), "r"(b0), "r"(b1));
}

// ===========================================================================
// Fused prep kernel: W2 fragments (idx < 4096), W1 fragments (idx >= 4096)
// ===========================================================================
__global__ void pack_w_kernel(const float* __restrict__ W1,
                              const float* __restrict__ W2)
{
    const int idx = blockIdx.x * blockDim.x + threadIdx.x;   // 0..12287
    if (idx >= 12288) return;
    const int lane = idx & 31;
    const int ki   = (idx >> 5) & 7;
    const int g    = lane >> 2;
    const int t    = lane & 3;
    if (idx < 4096) {
        const int ni = idx >> 8;
        const float* w = W2 + (size_t)(ni * 8 + g) * F + ki * 16;
        uint2 v;
        v.x = h2pack(__ldg(&w[2 * t]),     __ldg(&w[2 * t + 1]));
        v.y = h2pack(__ldg(&w[2 * t + 8]), __ldg(&w[2 * t + 9]));
        g_W2f[idx] = v;
    } else {
        const int id2 = idx - 4096;
        const int ni  = id2 >> 8;
        const int j2  = ni * 8 + g;
        const float* w = W1 + (size_t)(j2 & 127) * 256 + ((j2 >> 7) << 7) + ki * 16;
        uint2 v;
        v.x = h2pack(__ldg(&w[2 * t]),     __ldg(&w[2 * t + 1]));
        v.y = h2pack(__ldg(&w[2 * t + 8]), __ldg(&w[2 * t + 9]));
        g_W1f[id2] = v;
    }
}

// ===========================================================================
// Node kernel (exact R11/R8 form, b1s in smem): [A|B] = h @ W1^T
// fp16 fragment tile layout: tile = mi*8 + ki, stride 528 B
// ===========================================================================
#define XSF_WORDS   (64 * 132)
#define NODE_SMEM_B ((XSF_WORDS + 128) * 4 + 16)

__global__ void __launch_bounds__(256, 2)
node_mma_kernel(const float* __restrict__ h,
                const float* __restrict__ b1,
                int n_nodes)
{
    extern __shared__ uint32_t sm[];
    uint32_t* HsF = sm;
    float*    b1s = (float*)(sm + XSF_WORDS);

    const int tid  = threadIdx.x;
    const int lane = tid & 31;
    const int warp = tid >> 5;
    const int g    = lane >> 2;
    const int t    = lane & 3;
    const int base = blockIdx.x * 128;

    if (tid < 128) b1s[tid] = __ldg(&b1[tid]);

    #pragma unroll
    for (int p = 0; p < 2; p++) {
        const int tile = p * 32 + warp * 4 + (lane & 3);
        const int gg   = lane >> 2;
        const int mi   = tile >> 3;
        const int kc   = (tile & 7) * 16;
        const int rA   = mi * 16 + gg;
        const int rB   = rA + 8;
        const float mA = ((base + rA) < n_nodes) ? 1.0f : 0.0f;
        const float mB = ((base + rB) < n_nodes) ? 1.0f : 0.0f;
        const int  nA  = ((base + rA) < n_nodes) ? (base + rA) : 0;
        const int  nB  = ((base + rB) < n_nodes) ? (base + rB) : 0;

        float xA[16], xB[16];
        {
            const float4* pa = (const float4*)(h + (size_t)nA * F + kc);
            const float4* pb = (const float4*)(h + (size_t)nB * F + kc);
            #pragma unroll
            for (int q = 0; q < 4; q++) {
                float4 a = __ldg(pa + q);
                float4 b = __ldg(pb + q);
                xA[q*4+0] = a.x * mA; xA[q*4+1] = a.y * mA;
                xA[q*4+2] = a.z * mA; xA[q*4+3] = a.w * mA;
                xB[q*4+0] = b.x * mB; xB[q*4+1] = b.y * mB;
                xB[q*4+2] = b.z * mB; xB[q*4+3] = b.w * mB;
            }
        }

        char* tb = (char*)HsF + (size_t)tile * 528 + gg * 64;
        #pragma unroll
        for (int j = 0; j < 4; j++) {
            uint4 q;
            q.x = h2pack(xA[2*j],     xA[2*j + 1]);
            q.y = h2pack(xB[2*j],     xB[2*j + 1]);
            q.z = h2pack(xA[2*j + 8], xA[2*j + 9]);
            q.w = h2pack(xB[2*j + 8], xB[2*j + 9]);
            *(uint4*)(tb + j * 16) = q;
        }
    }
    __syncthreads();

    const int mq = warp & 3;

    for (int np = (warp >> 2); np < 4; np += 2) {
        float acc[2][8][4];
        #pragma unroll
        for (int im = 0; im < 2; im++)
            #pragma unroll
            for (int in = 0; in < 8; in++)
                #pragma unroll
                for (int c = 0; c < 4; c++) acc[im][in][c] = 0.0f;

        #pragma unroll
        for (int ki = 0; ki < 8; ki++) {
            uint2 bf[8];
            #pragma unroll
            for (int in = 0; in < 8; in++)
                bf[in] = __ldg(&g_W1f[(((np * 8 + in) << 3) + ki) * 32 + lane]);

            uint4 aq0 = *(const uint4*)((const char*)HsF +
                         (size_t)((mq * 2 + 0) * 8 + ki) * 528 + lane * 16);
            uint4 aq1 = *(const uint4*)((const char*)HsF +
                         (size_t)((mq * 2 + 1) * 8 + ki) * 528 + lane * 16);

            #pragma unroll
            for (int in = 0; in < 8; in++) {
                mma_f16(acc[0][in][0], acc[0][in][1], acc[0][in][2], acc[0][in][3],
                        aq0.x, aq0.y, aq0.z, aq0.w, bf[in].x, bf[in].y);
                mma_f16(acc[1][in][0], acc[1][in][1], acc[1][in][2], acc[1][in][3],
                        aq1.x, aq1.y, aq1.z, aq1.w, bf[in].x, bf[in].y);
            }
        }

        const int nb = np * 64;
        #pragma unroll
        for (int im = 0; im < 2; im++) {
            const int r0 = mq * 32 + im * 16 + g;
            const int n0 = base + r0;
            const int n1 = n0 + 8;
            #pragma unroll
            for (int in = 0; in < 8; in++) {
                const int col0 = nb + in * 8 + 2 * t;
                const bool isA = (col0 < 128);
                const float bb0 = isA ? b1s[col0]     : 0.0f;
                const float bb1 = isA ? b1s[col0 + 1] : 0.0f;
                __half* dst = isA ? g_Ah : g_Bh;
                const int  cc  = isA ? col0 : (col0 - 128);
                if (n0 < n_nodes) {
                    __half2 v = __floats2half2_rn(acc[im][in][0] + bb0,
                                                  acc[im][in][1] + bb1);
                    *(__half2*)(dst + (size_t)n0 * F + cc) = v;
                }
                if (n1 < n_nodes) {
                    __half2 v = __floats2half2_rn(acc[im][in][2] + bb0,
                                                  acc[im][in][3] + bb1);
                    *(__half2*)(dst + (size_t)n1 * F + cc) = v;
                }
            }
        }
    }
}

// ===========================================================================
// Edge kernel v3: 256 edges/block (4 tiles of 64), 256 threads, 2 blocks/SM.
// 8 warps: mq = warp&1 (32m), nt = warp>>1 (32n). B-fragments (bf[4][8])
// loaded ONCE and held in registers across all 4 tiles (tile-invariant).
// Per tile: producer = 1 task/thread (32 subtiles x 8 gg), 2 barriers.
// ===========================================================================
#define EPT         64
#define TPB         4
#define XSF2_WORDS  (32 * 132)
#define SS_BASE     XSF2_WORDS
#define DS_BASE     (SS_BASE + 256)
#define B2_BASE     (DS_BASE + 256)
#define W3_BASE     (B2_BASE + 128)
#define ES_BASE     (W3_BASE + 128)
#define EDGE_WORDS  (ES_BASE + 64)
#define EDGE_SMEM_B (EDGE_WORDS * 4)

__global__ void __launch_bounds__(256, 2)
edge_mma_kernel(const int*   __restrict__ src,
                const int*   __restrict__ dst,
                const float* __restrict__ b2,
                const float* __restrict__ W3,
                const float* __restrict__ b3,
                float*       __restrict__ out,
                int n_edges)
{
    extern __shared__ uint32_t sm[];
    uint32_t* XsF  = sm;
    int*      ss   = (int*)(sm + SS_BASE);
    int*      ds   = (int*)(sm + DS_BASE);
    float*    b2s  = (float*)(sm + B2_BASE);
    float*    w3s  = (float*)(sm + W3_BASE);
    float*    esum = (float*)(sm + ES_BASE);

    const int tid  = threadIdx.x;
    const int lane = tid & 31;
    const int warp = tid >> 5;
    const int g    = lane >> 2;
    const int t    = lane & 3;
    const int blk_base = blockIdx.x * (EPT * TPB);
    const float b3v = __ldg(&b3[0]);

    if (tid < 128) {
        b2s[tid] = __ldg(&b2[tid]);
        w3s[tid] = __ldg(&W3[tid]);
    }
    {
        const int e = blk_base + tid;
        const bool ok = (e < n_edges);
        ss[tid] = ok ? __ldg(&src[e]) : 0;
        ds[tid] = ok ? __ldg(&dst[e]) : 0;
    }
    if (tid < 64) esum[tid] = b3v;

    // persistent B fragments: warp covers n-tile nt (32 cols)
    const int mq = warp & 1;
    const int nt = warp >> 1;     // 0..3
    uint2 bf[4][8];
    #pragma unroll
    for (int in = 0; in < 4; in++)
        #pragma unroll
        for (int ki = 0; ki < 8; ki++)
            bf[in][ki] = __ldg(&g_W2f[(((nt * 4 + in) << 3) + ki) * 32 + lane]);

    __syncthreads();

    // producer task (fixed per thread): subtile + row group
    const int ptile = warp * 4 + (lane & 3);   // 0..31
    const int pgg   = lane >> 2;
    const int pmi   = ptile >> 3;              // 0..3
    const int pkc   = (ptile & 7) * 16;
    const int prA   = pmi * 16 + pgg;
    const int prB   = prA + 8;

    for (int tt = 0; tt < TPB; tt++) {
        // ---- producer: gather + combine + STS (1 task/thread) ----
        {
            const int toff = tt * EPT;
            const __half2 mA = __float2half2_rn(((blk_base + toff + prA) < n_edges) ? 1.0f : 0.0f);
            const __half2 mB = __float2half2_rn(((blk_base + toff + prB) < n_edges) ? 1.0f : 0.0f);

            __half2 pA[8], pB[8];
            {
                const uint4* pa = (const uint4*)(g_Ah + (size_t)ss[toff + prA] * F + pkc);
                const uint4* pb = (const uint4*)(g_Bh + (size_t)ds[toff + prA] * F + pkc);
                uint4 a0 = __ldg(pa), a1 = __ldg(pa + 1);
                uint4 b0 = __ldg(pb), b1 = __ldg(pb + 1);
                pA[0] = combh2(a0.x, b0.x, mA); pA[1] = combh2(a0.y, b0.y, mA);
                pA[2] = combh2(a0.z, b0.z, mA); pA[3] = combh2(a0.w, b0.w, mA);
                pA[4] = combh2(a1.x, b1.x, mA); pA[5] = combh2(a1.y, b1.y, mA);
                pA[6] = combh2(a1.z, b1.z, mA); pA[7] = combh2(a1.w, b1.w, mA);
            }
            {
                const uint4* pa = (const uint4*)(g_Ah + (size_t)ss[toff + prB] * F + pkc);
                const uint4* pb = (const uint4*)(g_Bh + (size_t)ds[toff + prB] * F + pkc);
                uint4 a0 = __ldg(pa), a1 = __ldg(pa + 1);
                uint4 b0 = __ldg(pb), b1 = __ldg(pb + 1);
                pB[0] = combh2(a0.x, b0.x, mB); pB[1] = combh2(a0.y, b0.y, mB);
                pB[2] = combh2(a0.z, b0.z, mB); pB[3] = combh2(a0.w, b0.w, mB);
                pB[4] = combh2(a1.x, b1.x, mB); pB[5] = combh2(a1.y, b1.y, mB);
                pB[6] = combh2(a1.z, b1.z, mB); pB[7] = combh2(a1.w, b1.w, mB);
            }

            char* tb = (char*)XsF + (size_t)ptile * 528 + pgg * 64;
            #pragma unroll
            for (int j = 0; j < 4; j++) {
                uint4 q;
                q.x = h2u(pA[j]);     q.y = h2u(pB[j]);
                q.z = h2u(pA[j + 4]); q.w = h2u(pB[j + 4]);
                *(uint4*)(tb + j * 16) = q;
            }
        }
        __syncthreads();

        // ---- MMA: warp (mq, nt), 32m x 32n ----
        float acc[2][4][4];
        #pragma unroll
        for (int im = 0; im < 2; im++)
            #pragma unroll
            for (int in = 0; in < 4; in++)
                #pragma unroll
                for (int c = 0; c < 4; c++) acc[im][in][c] = 0.0f;

        #pragma unroll
        for (int ki = 0; ki < 8; ki++) {
            uint4 aq0 = *(const uint4*)((const char*)XsF +
                         (size_t)((mq * 2 + 0) * 8 + ki) * 528 + lane * 16);
            uint4 aq1 = *(const uint4*)((const char*)XsF +
                         (size_t)((mq * 2 + 1) * 8 + ki) * 528 + lane * 16);

            #pragma unroll
            for (int in = 0; in < 4; in++) {
                mma_f16(acc[0][in][0], acc[0][in][1], acc[0][in][2], acc[0][in][3],
                        aq0.x, aq0.y, aq0.z, aq0.w, bf[in][ki].x, bf[in][ki].y);
                mma_f16(acc[1][in][0], acc[1][in][1], acc[1][in][2], acc[1][in][3],
                        aq1.x, aq1.y, aq1.z, aq1.w, bf[in][ki].x, bf[in][ki].y);
            }
        }

        // ---- epilogue: relu(D+b2)*W3 fold, reduce, atomic combine ----
        #pragma unroll
        for (int im = 0; im < 2; im++) {
            float p0 = 0.0f, p1 = 0.0f;
            #pragma unroll
            for (int in = 0; in < 4; in++) {
                const int col0 = nt * 32 + in * 8 + 2 * t;
                const float bb0 = b2s[col0], bb1 = b2s[col0 + 1];
                const float w0  = w3s[col0], w1  = w3s[col0 + 1];
                p0 = fmaf(fmaxf(acc[im][in][0] + bb0, 0.f), w0, p0);
                p0 = fmaf(fmaxf(acc[im][in][1] + bb1, 0.f), w1, p0);
                p1 = fmaf(fmaxf(acc[im][in][2] + bb0, 0.f), w0, p1);
                p1 = fmaf(fmaxf(acc[im][in][3] + bb1, 0.f), w1, p1);
            }
            p0 += __shfl_xor_sync(0xFFFFFFFFu, p0, 1);
            p0 += __shfl_xor_sync(0xFFFFFFFFu, p0, 2);
            p1 += __shfl_xor_sync(0xFFFFFFFFu, p1, 1);
            p1 += __shfl_xor_sync(0xFFFFFFFFu, p1, 2);
            if (t == 0) {
                atomicAdd(&esum[mq * 32 + im * 16 + g],     p0);
                atomicAdd(&esum[mq * 32 + im * 16 + g + 8], p1);
            }
        }
        __syncthreads();

        // ---- write out + reset esum (ordered vs next atomics by producer sync) ----
        if (tid < 64) {
            const int e = blk_base + tt * EPT + tid;
            if (e < n_edges) out[e] = esum[tid];
            esum[tid] = b3v;
        }
    }
}

// ===========================================================================
// launch: inputs: h, src, dst, W1, b1, W2, b2, W3, b3 ; out: [n_edges] f32
// ===========================================================================
extern "C" void kernel_launch(void* const* d_in, const int* in_sizes, int n_in,
                              void* d_out, int out_size)
{
    const float* h   = (const float*)d_in[0];
    const int*   src = (const int*)  d_in[1];
    const int*   dst = (const int*)  d_in[2];
    const float* W1  = (const float*)d_in[3];
    const float* b1  = (const float*)d_in[4];
    const float* W2  = (const float*)d_in[5];
    const float* b2  = (const float*)d_in[6];
    const float* W3  = (const float*)d_in[7];
    const float* b3  = (const float*)d_in[8];
    float*       out = (float*)d_out;

    const int n_nodes = in_sizes[0] / F;
    const int n_edges = in_sizes[1];

    cudaFuncSetAttribute(node_mma_kernel,
                         cudaFuncAttributeMaxDynamicSharedMemorySize, NODE_SMEM_B);
    cudaFuncSetAttribute(edge_mma_kernel,
                         cudaFuncAttributeMaxDynamicSharedMemorySize, EDGE_SMEM_B);

    pack_w_kernel<<<48, 256>>>(W1, W2);

    const int gridA = (n_nodes + 127) / 128;
    node_mma_kernel<<<gridA, 256, NODE_SMEM_B>>>(h, b1, n_nodes);

    const int gridB = (n_edges + (EPT * TPB) - 1) / (EPT * TPB);
    edge_mma_kernel<<<gridB, 256, EDGE_SMEM_B>>>(src, dst, b2, W3, b3, out, n_edges);
}

// round 17
// speedup vs baseline: 1.1564x; 1.1564x over previous
#include <cuda_runtime.h>
#include <cuda_fp16.h>
#include <cstdint>

#define NN_MAX   100000
#define F        128

// Scratch (fp16): A[n][j] = W1[:,:128]@h[n] + b1 ; B[n][j] = W1[:,128:]@h[n]
__device__ __half g_Ah[NN_MAX * F];
__device__ __half g_Bh[NN_MAX * F];

// fp16 b-fragments for m16n8k16 (row.col), uint2 per k-step:
//   b0 = {W[n][kc+2t], W[n][kc+2t+1]}, b1 = {W[n][kc+2t+8], W[n][kc+2t+9]},
//   n = ni*8 + (lane>>2), kc = ki*16
__device__ uint2 g_W2f[16 * 8 * 32];
__device__ uint2 g_W1f[32 * 8 * 32];

// ---------------------------------------------------------------------------
__device__ __forceinline__ uint32_t h2pack(float lo, float hi) {
    __half2 h = __floats2half2_rn(lo, hi);
    return *reinterpret_cast<uint32_t*>(&h);
}
__device__ __forceinline__ uint32_t h2u(__half2 h) {
    return *reinterpret_cast<uint32_t*>(&h);
}
__device__ __forceinline__ __half2 combh2(uint32_t a, uint32_t b, __half2 m) {
    __half2 ha = *reinterpret_cast<__half2*>(&a);
    __half2 hb = *reinterpret_cast<__half2*>(&b);
    const __half2 z = __float2half2_rn(0.0f);
    return __hmul2(__hmax2(__hadd2(ha, hb), z), m);
}

__device__ __forceinline__ void mma_f16(float& c0, float& c1, float& c2, float& c3,
                                        uint32_t a0, uint32_t a1, uint32_t a2, uint32_t a3,
                                        uint32_t b0, uint32_t b1)
{
    asm volatile(
        "mma.sync.aligned.m16n8k16.row.col.f32.f16.f16.f32 "
        "{%0,%1,%2,%3}, {%4,%5,%6,%7}, {%8,%9}, {%0,%1,%2,%3};\n"
        : "+f"(c0), "+f"(c1), "+f"(c2), "+f"(c3)
        : "r"(a0), "r"(a1), "r"(a2), "r"(a3), "r"(b0), "r"(b1));
}

// ===========================================================================
// Fused prep kernel: W2 fragments (idx < 4096), W1 fragments (idx >= 4096)
// ===========================================================================
__global__ void pack_w_kernel(const float* __restrict__ W1,
                              const float* __restrict__ W2)
{
    const int idx = blockIdx.x * blockDim.x + threadIdx.x;   // 0..12287
    if (idx >= 12288) return;
    const int lane = idx & 31;
    const int ki   = (idx >> 5) & 7;
    const int g    = lane >> 2;
    const int t    = lane & 3;
    if (idx < 4096) {
        const int ni = idx >> 8;
        const float* w = W2 + (size_t)(ni * 8 + g) * F + ki * 16;
        uint2 v;
        v.x = h2pack(__ldg(&w[2 * t]),     __ldg(&w[2 * t + 1]));
        v.y = h2pack(__ldg(&w[2 * t + 8]), __ldg(&w[2 * t + 9]));
        g_W2f[idx] = v;
    } else {
        const int id2 = idx - 4096;
        const int ni  = id2 >> 8;
        const int j2  = ni * 8 + g;
        const float* w = W1 + (size_t)(j2 & 127) * 256 + ((j2 >> 7) << 7) + ki * 16;
        uint2 v;
        v.x = h2pack(__ldg(&w[2 * t]),     __ldg(&w[2 * t + 1]));
        v.y = h2pack(__ldg(&w[2 * t + 8]), __ldg(&w[2 * t + 9]));
        g_W1f[id2] = v;
    }
}

// ===========================================================================
// Node kernel: [A|B] = h @ W1^T. Smem-staged coalesced output.
// Iteration it covers output cols [128it, 128it+128) = g_Ah (it=0) / g_Bh (it=1).
// Out tile: 128 rows x pitch 68 words (272 B, 16B-aligned per row).
// ===========================================================================
#define XSF_WORDS   (64 * 132)
#define OUT_PITCH   68
#define OUT_WORDS   (128 * OUT_PITCH)
#define NODE_SMEM_B ((XSF_WORDS + OUT_WORDS + 128) * 4 + 16)

__global__ void __launch_bounds__(256, 2)
node_mma_kernel(const float* __restrict__ h,
                const float* __restrict__ b1,
                int n_nodes)
{
    extern __shared__ uint32_t sm[];
    uint32_t* HsF = sm;
    uint32_t* Out = sm + XSF_WORDS;
    float*    b1s = (float*)(sm + XSF_WORDS + OUT_WORDS);

    const int tid  = threadIdx.x;
    const int lane = tid & 31;
    const int warp = tid >> 5;
    const int g    = lane >> 2;
    const int t    = lane & 3;
    const int base = blockIdx.x * 128;

    if (tid < 128) b1s[tid] = __ldg(&b1[tid]);

    // producer: h -> fragment layout (R8 form)
    #pragma unroll
    for (int p = 0; p < 2; p++) {
        const int tile = p * 32 + warp * 4 + (lane & 3);
        const int gg   = lane >> 2;
        const int mi   = tile >> 3;
        const int kc   = (tile & 7) * 16;
        const int rA   = mi * 16 + gg;
        const int rB   = rA + 8;
        const float mA = ((base + rA) < n_nodes) ? 1.0f : 0.0f;
        const float mB = ((base + rB) < n_nodes) ? 1.0f : 0.0f;
        const int  nA  = ((base + rA) < n_nodes) ? (base + rA) : 0;
        const int  nB  = ((base + rB) < n_nodes) ? (base + rB) : 0;

        float xA[16], xB[16];
        {
            const float4* pa = (const float4*)(h + (size_t)nA * F + kc);
            const float4* pb = (const float4*)(h + (size_t)nB * F + kc);
            #pragma unroll
            for (int q = 0; q < 4; q++) {
                float4 a = __ldg(pa + q);
                float4 b = __ldg(pb + q);
                xA[q*4+0] = a.x * mA; xA[q*4+1] = a.y * mA;
                xA[q*4+2] = a.z * mA; xA[q*4+3] = a.w * mA;
                xB[q*4+0] = b.x * mB; xB[q*4+1] = b.y * mB;
                xB[q*4+2] = b.z * mB; xB[q*4+3] = b.w * mB;
            }
        }

        char* tb = (char*)HsF + (size_t)tile * 528 + gg * 64;
        #pragma unroll
        for (int j = 0; j < 4; j++) {
            uint4 q;
            q.x = h2pack(xA[2*j],     xA[2*j + 1]);
            q.y = h2pack(xB[2*j],     xB[2*j + 1]);
            q.z = h2pack(xA[2*j + 8], xA[2*j + 9]);
            q.w = h2pack(xB[2*j + 8], xB[2*j + 9]);
            *(uint4*)(tb + j * 16) = q;
        }
    }
    __syncthreads();

    const int mq = warp & 3;
    const int nq = warp >> 2;     // 0..1

    #pragma unroll
    for (int it = 0; it < 2; it++) {
        const int np = nq + 2 * it;          // 0..3; cols np*64..np*64+63
        float acc[2][8][4];
        #pragma unroll
        for (int im = 0; im < 2; im++)
            #pragma unroll
            for (int in = 0; in < 8; in++)
                #pragma unroll
                for (int c = 0; c < 4; c++) acc[im][in][c] = 0.0f;

        #pragma unroll
        for (int ki = 0; ki < 8; ki++) {
            uint2 bf[8];
            #pragma unroll
            for (int in = 0; in < 8; in++)
                bf[in] = __ldg(&g_W1f[(((np * 8 + in) << 3) + ki) * 32 + lane]);

            uint4 aq0 = *(const uint4*)((const char*)HsF +
                         (size_t)((mq * 2 + 0) * 8 + ki) * 528 + lane * 16);
            uint4 aq1 = *(const uint4*)((const char*)HsF +
                         (size_t)((mq * 2 + 1) * 8 + ki) * 528 + lane * 16);

            #pragma unroll
            for (int in = 0; in < 8; in++) {
                mma_f16(acc[0][in][0], acc[0][in][1], acc[0][in][2], acc[0][in][3],
                        aq0.x, aq0.y, aq0.z, aq0.w, bf[in].x, bf[in].y);
                mma_f16(acc[1][in][0], acc[1][in][1], acc[1][in][2], acc[1][in][3],
                        aq1.x, aq1.y, aq1.z, aq1.w, bf[in].x, bf[in].y);
            }
        }

        // stage acc into Out tile (half-cols nq*64 + in*8 + 2t -> word colh>>1)
        #pragma unroll
        for (int im = 0; im < 2; im++) {
            const int r0 = mq * 32 + im * 16 + g;
            #pragma unroll
            for (int in = 0; in < 8; in++) {
                const int colh = nq * 64 + in * 8 + 2 * t;   // col within 128-half slab
                const int colg = np * 64 + in * 8 + 2 * t;   // global output col
                const float bb0 = (it == 0) ? b1s[colg]     : 0.0f;
                const float bb1 = (it == 0) ? b1s[colg + 1] : 0.0f;
                Out[(r0)     * OUT_PITCH + (colh >> 1)] =
                    h2pack(acc[im][in][0] + bb0, acc[im][in][1] + bb1);
                Out[(r0 + 8) * OUT_PITCH + (colh >> 1)] =
                    h2pack(acc[im][in][2] + bb0, acc[im][in][3] + bb1);
            }
        }
        __syncthreads();

        // coalesced copy: Out (128 rows x 128 halves) -> g_Ah / g_Bh
        {
            __half* dst = (it == 0) ? g_Ah : g_Bh;
            #pragma unroll
            for (int k = 0; k < 8; k++) {
                const int idx = tid + 256 * k;      // 0..2047
                const int row = idx >> 4;
                const int q   = idx & 15;           // uint4 within row
                if ((base + row) < n_nodes) {
                    uint4 v = *(const uint4*)(Out + row * OUT_PITCH + q * 4);
                    *(uint4*)(dst + (size_t)(base + row) * F + q * 8) = v;
                }
            }
        }
        __syncthreads();
    }
}

// ===========================================================================
// Edge kernel (exact R11): 64 edges / 128 threads / 4 blocks per SM.
// Warp (mq = warp&1, nh = warp>>1): 32m x 64n, K=128.
// XsF2: 32 tiles (mi 0..3, ki 0..7), stride 528 B.
// ===========================================================================
#define XSF2_WORDS  (32 * 132)
#define EDGE_SMEM_B ((XSF2_WORDS + 64 * 3 + 128 * 2) * 4 + 16)

__global__ void __launch_bounds__(128, 4)
edge_mma_kernel(const int*   __restrict__ src,
                const int*   __restrict__ dst,
                const float* __restrict__ b2,
                const float* __restrict__ W3,
                const float* __restrict__ b3,
                float*       __restrict__ out,
                int n_edges)
{
    extern __shared__ uint32_t sm[];
    uint32_t* XsF  = sm;
    int*      ss   = (int*)(sm + XSF2_WORDS);
    int*      ds   = ss + 64;
    float*    b2s  = (float*)(ds + 64);
    float*    w3s  = b2s + 128;
    float*    esum = w3s + 128;

    const int tid  = threadIdx.x;
    const int lane = tid & 31;
    const int warp = tid >> 5;
    const int g    = lane >> 2;
    const int t    = lane & 3;
    const int base = blockIdx.x * 64;

    {
        b2s[tid] = __ldg(&b2[tid]);
        w3s[tid] = __ldg(&W3[tid]);
        if (tid < 64) {
            const int e = base + tid;
            const bool ok = (e < n_edges);
            ss[tid]   = ok ? __ldg(&src[e]) : 0;
            ds[tid]   = ok ? __ldg(&dst[e]) : 0;
            esum[tid] = __ldg(&b3[0]);
        }
    }
    __syncthreads();

    // producer: 2 tasks/thread over 32 tiles x 8 gg
    #pragma unroll
    for (int p = 0; p < 2; p++) {
        const int tile = p * 16 + warp * 4 + (lane & 3);   // 0..31
        const int gg   = lane >> 2;
        const int mi   = tile >> 3;                        // 0..3
        const int kc   = (tile & 7) * 16;
        const int rA   = mi * 16 + gg;
        const int rB   = rA + 8;
        const __half2 mA = __float2half2_rn(((base + rA) < n_edges) ? 1.0f : 0.0f);
        const __half2 mB = __float2half2_rn(((base + rB) < n_edges) ? 1.0f : 0.0f);

        __half2 pA[8], pB[8];
        {
            const uint4* pa = (const uint4*)(g_Ah + (size_t)ss[rA] * F + kc);
            const uint4* pb = (const uint4*)(g_Bh + (size_t)ds[rA] * F + kc);
            uint4 a0 = __ldg(pa), a1 = __ldg(pa + 1);
            uint4 b0 = __ldg(pb), b1 = __ldg(pb + 1);
            pA[0] = combh2(a0.x, b0.x, mA); pA[1] = combh2(a0.y, b0.y, mA);
            pA[2] = combh2(a0.z, b0.z, mA); pA[3] = combh2(a0.w, b0.w, mA);
            pA[4] = combh2(a1.x, b1.x, mA); pA[5] = combh2(a1.y, b1.y, mA);
            pA[6] = combh2(a1.z, b1.z, mA); pA[7] = combh2(a1.w, b1.w, mA);
        }
        {
            const uint4* pa = (const uint4*)(g_Ah + (size_t)ss[rB] * F + kc);
            const uint4* pb = (const uint4*)(g_Bh + (size_t)ds[rB] * F + kc);
            uint4 a0 = __ldg(pa), a1 = __ldg(pa + 1);
            uint4 b0 = __ldg(pb), b1 = __ldg(pb + 1);
            pB[0] = combh2(a0.x, b0.x, mB); pB[1] = combh2(a0.y, b0.y, mB);
            pB[2] = combh2(a0.z, b0.z, mB); pB[3] = combh2(a0.w, b0.w, mB);
            pB[4] = combh2(a1.x, b1.x, mB); pB[5] = combh2(a1.y, b1.y, mB);
            pB[6] = combh2(a1.z, b1.z, mB); pB[7] = combh2(a1.w, b1.w, mB);
        }

        char* tb = (char*)XsF + (size_t)tile * 528 + gg * 64;
        #pragma unroll
        for (int j = 0; j < 4; j++) {
            uint4 q;
            q.x = h2u(pA[j]);     q.y = h2u(pB[j]);
            q.z = h2u(pA[j + 4]); q.w = h2u(pB[j + 4]);
            *(uint4*)(tb + j * 16) = q;
        }
    }
    __syncthreads();

    const int mq = warp & 1;
    const int nh = warp >> 1;

    float acc[2][8][4];
    #pragma unroll
    for (int im = 0; im < 2; im++)
        #pragma unroll
        for (int in = 0; in < 8; in++)
            #pragma unroll
            for (int c = 0; c < 4; c++) acc[im][in][c] = 0.0f;

    #pragma unroll
    for (int ki = 0; ki < 8; ki++) {
        uint2 bf[8];
        #pragma unroll
        for (int in = 0; in < 8; in++)
            bf[in] = __ldg(&g_W2f[(((nh * 8 + in) << 3) + ki) * 32 + lane]);

        uint4 aq0 = *(const uint4*)((const char*)XsF +
                     (size_t)((mq * 2 + 0) * 8 + ki) * 528 + lane * 16);
        uint4 aq1 = *(const uint4*)((const char*)XsF +
                     (size_t)((mq * 2 + 1) * 8 + ki) * 528 + lane * 16);

        #pragma unroll
        for (int in = 0; in < 8; in++) {
            mma_f16(acc[0][in][0], acc[0][in][1], acc[0][in][2], acc[0][in][3],
                    aq0.x, aq0.y, aq0.z, aq0.w, bf[in].x, bf[in].y);
            mma_f16(acc[1][in][0], acc[1][in][1], acc[1][in][2], acc[1][in][3],
                    aq1.x, aq1.y, aq1.z, aq1.w, bf[in].x, bf[in].y);
        }
    }

    #pragma unroll
    for (int im = 0; im < 2; im++) {
        float p0 = 0.0f, p1 = 0.0f;
        #pragma unroll
        for (int in = 0; in < 8; in++) {
            const int col0 = nh * 64 + in * 8 + 2 * t;
            const float bb0 = b2s[col0], bb1 = b2s[col0 + 1];
            const float w0  = w3s[col0], w1  = w3s[col0 + 1];
            p0 = fmaf(fmaxf(acc[im][in][0] + bb0, 0.f), w0, p0);
            p0 = fmaf(fmaxf(acc[im][in][1] + bb1, 0.f), w1, p0);
            p1 = fmaf(fmaxf(acc[im][in][2] + bb0, 0.f), w0, p1);
            p1 = fmaf(fmaxf(acc[im][in][3] + bb1, 0.f), w1, p1);
        }
        p0 += __shfl_xor_sync(0xFFFFFFFFu, p0, 1);
        p0 += __shfl_xor_sync(0xFFFFFFFFu, p0, 2);
        p1 += __shfl_xor_sync(0xFFFFFFFFu, p1, 1);
        p1 += __shfl_xor_sync(0xFFFFFFFFu, p1, 2);
        if (t == 0) {
            atomicAdd(&esum[mq * 32 + im * 16 + g],     p0);
            atomicAdd(&esum[mq * 32 + im * 16 + g + 8], p1);
        }
    }
    __syncthreads();

    if (tid < 64) {
        const int e = base + tid;
        if (e < n_edges) out[e] = esum[tid];
    }
}

// ===========================================================================
// launch: inputs: h, src, dst, W1, b1, W2, b2, W3, b3 ; out: [n_edges] f32
// ===========================================================================
extern "C" void kernel_launch(void* const* d_in, const int* in_sizes, int n_in,
                              void* d_out, int out_size)
{
    const float* h   = (const float*)d_in[0];
    const int*   src = (const int*)  d_in[1];
    const int*   dst = (const int*)  d_in[2];
    const float* W1  = (const float*)d_in[3];
    const float* b1  = (const float*)d_in[4];
    const float* W2  = (const float*)d_in[5];
    const float* b2  = (const float*)d_in[6];
    const float* W3  = (const float*)d_in[7];
    const float* b3  = (const float*)d_in[8];
    float*       out = (float*)d_out;

    const int n_nodes = in_sizes[0] / F;
    const int n_edges = in_sizes[1];

    cudaFuncSetAttribute(node_mma_kernel,
                         cudaFuncAttributeMaxDynamicSharedMemorySize, NODE_SMEM_B);
    cudaFuncSetAttribute(edge_mma_kernel,
                         cudaFuncAttributeMaxDynamicSharedMemorySize, EDGE_SMEM_B);

    pack_w_kernel<<<48, 256>>>(W1, W2);

    const int gridA = (n_nodes + 127) / 128;
    node_mma_kernel<<<gridA, 256, NODE_SMEM_B>>>(h, b1, n_nodes);

    const int gridB = (n_edges + 63) / 64;
    edge_mma_kernel<<<gridB, 128, EDGE_SMEM_B>>>(src, dst, b2, W3, b3, out, n_edges);
}